// round 6
// baseline (speedup 1.0000x reference)
#include <cuda_runtime.h>
#include <math.h>
#include <stdint.h>

#define NQ 4096
#define NS 4096
#define D  1024
#define KC 128
#define EPSF 1e-12f
#define KSP 4            // split-K for dots GEMM
#define KPB (D / KSP)    // 256 K per split
#define CH  32           // K chunk
#define NTILE (NQ / 128) // 32 query tiles

// ---------------- device scratch ----------------
__device__ float d_q2[NQ];
__device__ float d_d2self[NQ];
__device__ int   d_cnt[KC];
__device__ float d_S2c[KC];
__device__ float d_mus[KC * D];
__device__ float d_mus2[KC];
__device__ float d_pn2[KC];
__device__ float d_invc[KC];
__device__ float d_dotsp[KSP * NQ * KC];   // [s][i][k] split partials
__device__ float d_psum[NTILE];
__device__ int   d_tilecnt[NTILE];
__device__ int   d_done;

// ---------------- helpers ----------------
__device__ __forceinline__ float wsum(float v) {
#pragma unroll
    for (int o = 16; o; o >>= 1) v += __shfl_xor_sync(0xffffffffu, v, o);
    return v;
}
__device__ __forceinline__ float wmax(float v) {
#pragma unroll
    for (int o = 16; o; o >>= 1) v = fmaxf(v, __shfl_xor_sync(0xffffffffu, v, o));
    return v;
}
__device__ __forceinline__ uint32_t f2tf32(float f) {
    uint32_t r;
    asm("cvt.rna.tf32.f32 %0, %1;" : "=r"(r) : "f"(f));
    return r;
}

// ---------------- K1: q2 + self distance; also resets counters ------------
// grid NQ/8, block 256. q2[i] = |xq_i|^2 ; d2self[i] = |xq_i - xs_{pos_i}|^2
__global__ __launch_bounds__(256) void k_norms(const float* __restrict__ xq,
                                               const float* __restrict__ xs,
                                               const int* __restrict__ pos) {
    if (blockIdx.x == 0) {
        if (threadIdx.x < NTILE) d_tilecnt[threadIdx.x] = 0;
        if (threadIdx.x == NTILE) d_done = 0;
    }
    int i = blockIdx.x * 8 + (threadIdx.x >> 5);
    int ln = threadIdx.x & 31;
    int p = __ldg(pos + i);
    const float4* qr = (const float4*)(xq + (size_t)i * D);
    const float4* pr = (const float4*)(xs + (size_t)p * D);
    float q2 = 0.f, ds = 0.f;
#pragma unroll
    for (int l = 0; l < 8; l++) {
        int idx = ln + 32 * l;
        float4 q = qr[idx];
        q2 += q.x * q.x + q.y * q.y + q.z * q.z + q.w * q.w;
        float4 b = pr[idx];
        float dx = q.x - b.x, dy = q.y - b.y, dz = q.z - b.z, dw = q.w - b.w;
        ds += dx * dx + dy * dy + dz * dz + dw * dw;
    }
    q2 = wsum(q2); ds = wsum(ds);
    if (ln == 0) {
        d_q2[i] = q2;
        d_d2self[i] = ds;
    }
}

// ---------------- K2: fused per-class stats + feature sums ----------------
// grid KC, block 256. Ordered compaction, then mus, cnt, S2c, |mus|^2, ...
__global__ __launch_bounds__(256) void k_mus(const float* __restrict__ xs,
                                             const int* __restrict__ ys) {
    int c = blockIdx.x, t = threadIdx.x;
    __shared__ int rows[NS];
    __shared__ int sc[256];
    __shared__ float red[256];

    int myy[16];
    int j0 = t * 16;
#pragma unroll
    for (int j = 0; j < 16; j++) myy[j] = ys[j0 + j];
    int count = 0;
#pragma unroll
    for (int j = 0; j < 16; j++) count += (myy[j] == c);

    sc[t] = count;
    __syncthreads();
    for (int o = 1; o < 256; o <<= 1) {
        int v = (t >= o) ? sc[t - o] : 0;
        __syncthreads();
        sc[t] += v;
        __syncthreads();
    }
    int off = sc[t] - count;
    int cnt = sc[255];
#pragma unroll
    for (int j = 0; j < 16; j++) {
        if (myy[j] == c) rows[off++] = j0 + j;
    }
    __syncthreads();

    float4 acc = make_float4(0.f, 0.f, 0.f, 0.f);
    float sq = 0.f;
    for (int r = 0; r < cnt; r++) {
        float4 v = ((const float4*)(xs + (size_t)rows[r] * D))[t];
        acc.x += v.x; acc.y += v.y; acc.z += v.z; acc.w += v.w;
        sq += v.x * v.x + v.y * v.y + v.z * v.z + v.w * v.w;
    }
    ((float4*)(d_mus + (size_t)c * D))[t] = acc;

    red[t] = acc.x * acc.x + acc.y * acc.y + acc.z * acc.z + acc.w * acc.w;
    __syncthreads();
    for (int s = 128; s; s >>= 1) {
        if (t < s) red[t] += red[t + s];
        __syncthreads();
    }
    float m2 = red[0];
    __syncthreads();
    red[t] = sq;
    __syncthreads();
    for (int s = 128; s; s >>= 1) {
        if (t < s) red[t] += red[t + s];
        __syncthreads();
    }
    if (t == 0) {
        d_S2c[c] = red[0];
        d_cnt[c] = cnt;
        d_mus2[c] = m2;
        float cc = fmaxf((float)cnt, 0.1f);
        d_invc[c] = 1.f / cc;
        d_pn2[c] = m2 / (cc * cc);
    }
}

// ---------------- K3: dots GEMM + fused finalize + final mean -------------
// grid (NTILE, KSP), block 256. Block tile 128x128, split-K over KPB.
// Last split block per tile finalizes the tile's 128 queries; last tile
// block reduces all tile partials and writes the loss.
__global__ __launch_bounds__(256) void k_dots(const float* __restrict__ xq,
                                              const int* __restrict__ yq,
                                              const int* __restrict__ ys,
                                              const int* __restrict__ pos,
                                              float* __restrict__ out) {
    __shared__ uint32_t As[128][36];
    __shared__ uint32_t Bs[128][36];

    int tile = blockIdx.x;
    int qb = tile * 128;
    int sp = blockIdx.y;
    int t = threadIdx.x;
    int lane = t & 31, wid = t >> 5;
    int wm = (wid >> 2) * 64;
    int wn = (wid & 3) * 32;
    int g = lane >> 2, ci = lane & 3;

    int lrow = t >> 1;
    int lcol0 = (t & 1) * 16;

    float acc[4][4][4];
#pragma unroll
    for (int a = 0; a < 4; a++)
#pragma unroll
        for (int b = 0; b < 4; b++)
#pragma unroll
            for (int r = 0; r < 4; r++) acc[a][b][r] = 0.f;

    const float* Aptr = xq + (size_t)(qb + lrow) * D + sp * KPB + lcol0;
    const float* Bptr = d_mus + (size_t)lrow * D + sp * KPB + lcol0;

    float4 aR[4], bR[4];
#pragma unroll
    for (int i = 0; i < 4; i++) {
        aR[i] = ((const float4*)Aptr)[i];
        bR[i] = ((const float4*)Bptr)[i];
    }

    for (int ch = 0; ch < KPB / CH; ch++) {
        __syncthreads();
#pragma unroll
        for (int i = 0; i < 4; i++) {
            uint4 ua, ub;
            ua.x = f2tf32(aR[i].x); ua.y = f2tf32(aR[i].y);
            ua.z = f2tf32(aR[i].z); ua.w = f2tf32(aR[i].w);
            ub.x = f2tf32(bR[i].x); ub.y = f2tf32(bR[i].y);
            ub.z = f2tf32(bR[i].z); ub.w = f2tf32(bR[i].w);
            *(uint4*)&As[lrow][lcol0 + 4 * i] = ua;
            *(uint4*)&Bs[lrow][lcol0 + 4 * i] = ub;
        }
        __syncthreads();
        if (ch + 1 < KPB / CH) {
            const float* An = Aptr + (ch + 1) * CH;
            const float* Bn = Bptr + (ch + 1) * CH;
#pragma unroll
            for (int i = 0; i < 4; i++) {
                aR[i] = ((const float4*)An)[i];
                bR[i] = ((const float4*)Bn)[i];
            }
        }
#pragma unroll
        for (int k0 = 0; k0 < CH; k0 += 8) {
            uint32_t af[4][4], bf[4][2];
#pragma unroll
            for (int mt = 0; mt < 4; mt++) {
                int r = wm + mt * 16 + g;
                af[mt][0] = As[r][k0 + ci];
                af[mt][1] = As[r + 8][k0 + ci];
                af[mt][2] = As[r][k0 + ci + 4];
                af[mt][3] = As[r + 8][k0 + ci + 4];
            }
#pragma unroll
            for (int nt = 0; nt < 4; nt++) {
                int r = wn + nt * 8 + g;
                bf[nt][0] = Bs[r][k0 + ci];
                bf[nt][1] = Bs[r][k0 + ci + 4];
            }
#pragma unroll
            for (int mt = 0; mt < 4; mt++)
#pragma unroll
                for (int nt = 0; nt < 4; nt++) {
                    asm volatile(
                        "mma.sync.aligned.m16n8k8.row.col.f32.tf32.tf32.f32 "
                        "{%0,%1,%2,%3}, {%4,%5,%6,%7}, {%8,%9}, {%0,%1,%2,%3};\n"
                        : "+f"(acc[mt][nt][0]), "+f"(acc[mt][nt][1]),
                          "+f"(acc[mt][nt][2]), "+f"(acc[mt][nt][3])
                        : "r"(af[mt][0]), "r"(af[mt][1]), "r"(af[mt][2]), "r"(af[mt][3]),
                          "r"(bf[nt][0]), "r"(bf[nt][1]));
                }
        }
    }

    // epilogue: [s][i][k] layout, coalesced float2 stores (R3-proven)
#pragma unroll
    for (int mt = 0; mt < 4; mt++)
#pragma unroll
        for (int nt = 0; nt < 4; nt++) {
            int row = qb + wm + mt * 16 + g;
            int col = wn + nt * 8 + 2 * ci;
            float* o = d_dotsp + ((size_t)sp * NQ + row) * KC + col;
            *(float2*)o = make_float2(acc[mt][nt][0], acc[mt][nt][1]);
            *(float2*)(o + 8 * KC) = make_float2(acc[mt][nt][2], acc[mt][nt][3]);
        }

    // ---- last split block for this tile finalizes its 128 queries ----
    __threadfence();
    __shared__ int slast;
    if (t == 0) slast = (atomicAdd(&d_tilecnt[tile], 1) == KSP - 1);
    __syncthreads();
    if (!slast) return;
    __threadfence();   // acquire: see peers' dotsp stores

    float wacc = 0.f;  // per-warp loss partial (fixed r order, lane-uniform)
#pragma unroll 1
    for (int r = 0; r < 16; r++) {
        int i = qb + wid * 16 + r;
        float q2 = d_q2[i];
        int p = __ldg(pos + i);
        int cnew = __ldg(ys + p);
        int cq = __ldg(yq + i);

        float logit[4];
        float lmax = -1e30f;
        float dotq_c = 0.f;
#pragma unroll
        for (int kk = 0; kk < 4; kk++) {
            int k = lane + 32 * kk;
            float dot = 0.f;
#pragma unroll
            for (int s = 0; s < KSP; s++)
                dot += d_dotsp[((size_t)s * NQ + i) * KC + k];
            if (k == cq) dotq_c = dot;
            float lg;
            if (k == cnew) {
                float Cc = fmaxf((float)d_cnt[cnew] - 1.f, 0.1f);
                float qp = (dot - q2) / Cc;
                float pp2 = (d_mus2[cnew] - 2.f * dot + q2) / (Cc * Cc);
                float dp2 = q2 - 2.f * qp + pp2;
                lg = -sqrtf(fmaxf(dp2, 0.f) + EPSF);
            } else {
                float d2 = fmaxf(q2 + d_pn2[k] - 2.f * dot * d_invc[k], 0.f);
                lg = -sqrtf(d2 + EPSF);
            }
            logit[kk] = lg;
            lmax = fmaxf(lmax, lg);
        }
        float mall = wmax(lmax);
        float e = 0.f;
#pragma unroll
        for (int kk = 0; kk < 4; kk++) e += expf(logit[kk] - mall);
        float tot = wsum(e);
        float dotq = wsum(dotq_c);

        // all lanes compute the same value (lane-uniform inputs)
        float neg = mall + logf(tot);
        int cntq = d_cnt[cq];
        float sumd2 = (float)cntq * q2 + d_S2c[cq] - 2.f * dotq;
        float numer = sumd2;
        float denom = (float)cntq;
        if (cq == cnew) {
            numer -= fmaxf(d_d2self[i], 0.f);
            denom -= 1.f;
            if (!(cntq > 1)) denom += 1.f;
        }
        float poslog = (denom > 0.f) ? (-0.5f * numer / denom) : 0.f;
        wacc += neg - poslog;
    }

    __shared__ float sh[8];
    if (lane == 0) sh[wid] = wacc;
    __syncthreads();
    __shared__ int sdone;
    if (t == 0) {
        float s = 0.f;
#pragma unroll
        for (int w = 0; w < 8; w++) s += sh[w];
        d_psum[tile] = s;
        __threadfence();
        sdone = (atomicAdd(&d_done, 1) == NTILE - 1);
    }
    __syncthreads();
    if (!sdone) return;
    __threadfence();   // acquire: see all tile partials

    if (wid == 0) {
        float v = (lane < NTILE) ? d_psum[lane] : 0.f;
        v = wsum(v);
        if (lane == 0) out[0] = v * (1.f / (float)NQ);
    }
}

// --------------------------------------------------------------------------
extern "C" void kernel_launch(void* const* d_in, const int* in_sizes, int n_in,
                              void* d_out, int out_size) {
    const float* xq  = (const float*)d_in[0];
    const int*   yq  = (const int*)d_in[1];
    const float* xs  = (const float*)d_in[2];
    const int*   ys  = (const int*)d_in[3];
    const int*   pos = (const int*)d_in[4];
    float* out = (float*)d_out;

    k_norms<<<NQ / 8, 256>>>(xq, xs, pos);
    k_mus<<<KC, 256>>>(xs, ys);
    k_dots<<<dim3(NTILE, KSP), 256>>>(xq, yq, ys, pos, out);
}